// round 4
// baseline (speedup 1.0000x reference)
#include <cuda_runtime.h>
#include <cstdint>

// Problem constants
#define DDIM 512
#define KCL  2048
#define NTOT 65536

// GEMM tiling: CTA 128x128, 512 threads (16 warps, 4x4), warp 32x32, BK=32.
#define BM 128
#define BN 128
#define BK 32
#define NPASS (KCL / BN)        // 16
#define NCH   (DDIM / BK)       // 16
#define TOTC  (NPASS * NCH)     // 256 flattened chunks

// Stage layout (floats): Ahi | Alo | Bhi | Blo, each 128x32
#define AHI_F 0
#define ALO_F 4096
#define BHI_F 8192
#define BLO_F 12288
#define STAGE_F 16384
#define SMEM_BYTES (2 * STAGE_F * 4)   // 128 KB, 2 stages

// Scratch (no cudaMalloc allowed)
__device__ float g_c2[KCL];
__device__ float g_x2[NTOT];

// ---------------------------------------------------------------------------
// Helpers
// ---------------------------------------------------------------------------
// tf32 two-term split: v = h + l (+ eps), both tf32-rounded fp32 values.
__device__ __forceinline__ void split2(float v, float& h, float& l) {
    uint32_t hu; asm("cvt.rna.tf32.f32 %0, %1;" : "=r"(hu) : "f"(v));
    h = __uint_as_float(hu);
    float r = v - h;
    uint32_t lu; asm("cvt.rna.tf32.f32 %0, %1;" : "=r"(lu) : "f"(r));
    l = __uint_as_float(lu);
}

__device__ __forceinline__ void mma8f(float* c, float a0, float a1, float a2,
                                      float a3, float b0, float b1) {
    asm volatile(
        "mma.sync.aligned.m16n8k8.row.col.f32.tf32.tf32.f32 "
        "{%0,%1,%2,%3}, {%4,%5,%6,%7}, {%8,%9}, {%0,%1,%2,%3};"
        : "+f"(c[0]), "+f"(c[1]), "+f"(c[2]), "+f"(c[3])
        : "r"(__float_as_uint(a0)), "r"(__float_as_uint(a1)),
          "r"(__float_as_uint(a2)), "r"(__float_as_uint(a3)),
          "r"(__float_as_uint(b0)), "r"(__float_as_uint(b1)));
}

// Writer: split 8 values (row r, logical cols 8c..8c+7) into hi/lo tiles.
// Tile layout: row-major 32 floats/row; within a row, logical col k stored at
// phys (k&3)*8 + (k>>2); 16B groups XOR-swizzled by (r&7). This makes each
// compute thread's per-(2 k-steps) fragment one conflict-free LDS.128.
__device__ __forceinline__ void sts_split8(float* hiB, float* loB, int r, int c,
                                           float4 v0, float4 v1) {
    const int rx = r & 7, ch = c >> 1, e0 = 2 * (c & 1);
    float* hb = hiB + r * 32 + e0;
    float* lb = loB + r * 32 + e0;
    float va[8] = {v0.x, v0.y, v0.z, v0.w, v1.x, v1.y, v1.z, v1.w};
    #pragma unroll
    for (int q = 0; q < 4; q++) {
        float h0, l0, h1, l1;
        split2(va[q],     h0, l0);
        split2(va[q + 4], h1, l1);
        int go = ((2 * q + ch) ^ rx) * 4;
        *(float2*)(hb + go) = make_float2(h0, h1);
        *(float2*)(lb + go) = make_float2(l0, l1);
    }
}

// ---------------------------------------------------------------------------
// Row squared-norms
// ---------------------------------------------------------------------------
__global__ void c2_kernel(const float* __restrict__ cl) {
    int warp = (blockIdx.x * blockDim.x + threadIdx.x) >> 5;
    int lane = threadIdx.x & 31;
    if (warp >= KCL) return;
    const float4* r = (const float4*)(cl + (size_t)warp * DDIM);
    float s = 0.f;
    #pragma unroll 4
    for (int i = lane; i < DDIM / 4; i += 32) {
        float4 v = r[i];
        s += v.x * v.x + v.y * v.y + v.z * v.z + v.w * v.w;
    }
    #pragma unroll
    for (int o = 16; o; o >>= 1) s += __shfl_xor_sync(~0u, s, o);
    if (lane == 0) g_c2[warp] = s;
}

__global__ void x2_kernel(const float* __restrict__ x, int N) {
    int warp = (blockIdx.x * blockDim.x + threadIdx.x) >> 5;
    int lane = threadIdx.x & 31;
    if (warp >= N) return;
    const float4* r = (const float4*)(x + (size_t)warp * DDIM);
    float s = 0.f;
    #pragma unroll 4
    for (int i = lane; i < DDIM / 4; i += 32) {
        float4 v = r[i];
        s += v.x * v.x + v.y * v.y + v.z * v.z + v.w * v.w;
    }
    #pragma unroll
    for (int o = 16; o; o >>= 1) s += __shfl_xor_sync(~0u, s, o);
    if (lane == 0) g_x2[warp] = s;
}

__global__ void zero_kernel(float* p, int n) {
    int i = blockIdx.x * blockDim.x + threadIdx.x;
    if (i < n) p[i] = 0.f;
}

// ---------------------------------------------------------------------------
// mma.sync tf32 (3x split) distance GEMM + fused argmin.
// Pipeline per flattened chunk it = (pass, dc):
//   compute(stage it&1); split+STS regs(it+1) -> stage (it+1)&1; LDG(it+2).
// ---------------------------------------------------------------------------
__global__ void __launch_bounds__(512, 1)
assign_mma(const float* __restrict__ x, const float* __restrict__ cl,
           float* __restrict__ out_idx, float* __restrict__ out_loss,
           float invN) {
    extern __shared__ float smem[];
    __shared__ float sval[128][4];
    __shared__ int   sidx[128][4];

    const int tid  = threadIdx.x;
    const int lane = tid & 31;
    const int wid  = tid >> 5;
    const int wm   = wid & 3;      // 4 warp rows (32 m each)
    const int wn   = wid >> 2;     // 4 warp cols (32 n each)
    const int g    = lane >> 2;
    const int t4   = lane & 3;
    const int m0   = blockIdx.x * BM;

    // writer mapping: row wr, 8 contiguous logical cols at 8*wc
    const int wr = tid >> 2;
    const int wc = tid & 3;

    const float* gA = x + (size_t)m0 * DDIM;

    float acc[2][4][4];
    #pragma unroll
    for (int a = 0; a < 2; a++)
        #pragma unroll
        for (int b = 0; b < 4; b++)
            #pragma unroll
            for (int e = 0; e < 4; e++) acc[a][b][e] = 0.f;

    float bv[4];
    int   bi[4];
    #pragma unroll
    for (int i = 0; i < 4; i++) { bv[i] = 3.4e38f; bi[i] = 0; }

    float4 pa0, pa1, pb0, pb1;   // prefetch regs

    // LDG chunk c (A depends on dc only; B on pass too)
    #define LDGC(c) do {                                                        \
        int _dc = (c) & (NCH - 1);                                              \
        int _ps = (c) >> 4;                                                     \
        const float* _a = gA + (size_t)wr * DDIM + _dc * BK + wc * 8;           \
        pa0 = *(const float4*)_a;  pa1 = *(const float4*)(_a + 4);              \
        const float* _b = cl + (size_t)(_ps * BN + wr) * DDIM + _dc * BK + wc * 8; \
        pb0 = *(const float4*)_b;  pb1 = *(const float4*)(_b + 4);              \
    } while (0)

    #define STSC(stg) do {                                                      \
        sts_split8((stg) + AHI_F, (stg) + ALO_F, wr, wc, pa0, pa1);             \
        sts_split8((stg) + BHI_F, (stg) + BLO_F, wr, wc, pb0, pb1);             \
    } while (0)

    // prologue
    LDGC(0);
    STSC(smem);
    LDGC(1);
    __syncthreads();

    #pragma unroll 1
    for (int it = 0; it < TOTC; it++) {
        const float* stage = smem + (it & 1) * STAGE_F;
        const float4* Ah = (const float4*)(stage + AHI_F);
        const float4* Al = (const float4*)(stage + ALO_F);
        const float4* Bh = (const float4*)(stage + BHI_F);
        const float4* Bl = (const float4*)(stage + BLO_F);

        #pragma unroll
        for (int ks2 = 0; ks2 < 2; ks2++) {
            const int sw = (2 * t4 + ks2) ^ g;   // all fragment rows have row&7 == g
            float4 bh[4], bl[4];
            #pragma unroll
            for (int nt = 0; nt < 4; nt++) {
                int rb = wn * 32 + nt * 8 + g;
                bh[nt] = Bh[rb * 8 + sw];
                bl[nt] = Bl[rb * 8 + sw];
            }
            #pragma unroll
            for (int mt = 0; mt < 2; mt++) {
                int ra = wm * 32 + mt * 16 + g;
                float4 ah0 = Ah[ra * 8 + sw], ah1 = Ah[(ra + 8) * 8 + sw];
                float4 al0 = Al[ra * 8 + sw], al1 = Al[(ra + 8) * 8 + sw];
                #pragma unroll
                for (int nt = 0; nt < 4; nt++) {
                    // ks = 2*ks2 (elements .x/.y)
                    mma8f(acc[mt][nt], ah0.x, ah1.x, ah0.y, ah1.y, bh[nt].x, bh[nt].y);
                    mma8f(acc[mt][nt], ah0.x, ah1.x, ah0.y, ah1.y, bl[nt].x, bl[nt].y);
                    mma8f(acc[mt][nt], al0.x, al1.x, al0.y, al1.y, bh[nt].x, bh[nt].y);
                    // ks = 2*ks2+1 (elements .z/.w)
                    mma8f(acc[mt][nt], ah0.z, ah1.z, ah0.w, ah1.w, bh[nt].z, bh[nt].w);
                    mma8f(acc[mt][nt], ah0.z, ah1.z, ah0.w, ah1.w, bl[nt].z, bl[nt].w);
                    mma8f(acc[mt][nt], al0.z, al1.z, al0.w, al1.w, bh[nt].z, bh[nt].w);
                }
            }
        }

        if (it + 1 < TOTC) {
            float* ns = smem + ((it + 1) & 1) * STAGE_F;
            STSC(ns);
        }
        if (it + 2 < TOTC) LDGC(it + 2);

        if ((it & (NCH - 1)) == NCH - 1) {
            // end of pass: fold acc into running argmin, reset acc
            const int kc0 = (it >> 4) * BN;
            #pragma unroll
            for (int mt = 0; mt < 2; mt++)
                #pragma unroll
                for (int hm = 0; hm < 2; hm++) {
                    const int rs = mt * 2 + hm;
                    #pragma unroll
                    for (int nt = 0; nt < 4; nt++)
                        #pragma unroll
                        for (int e = 0; e < 2; e++) {
                            int col = kc0 + wn * 32 + nt * 8 + 2 * t4 + e;
                            float s = fmaf(-2.f, acc[mt][nt][hm * 2 + e],
                                           __ldg(&g_c2[col]));
                            if (s < bv[rs]) { bv[rs] = s; bi[rs] = col; }
                        }
                }
            #pragma unroll
            for (int a = 0; a < 2; a++)
                #pragma unroll
                for (int b = 0; b < 4; b++)
                    #pragma unroll
                    for (int e = 0; e < 4; e++) acc[a][b][e] = 0.f;
        }
        __syncthreads();
    }

    // quad (t4) reduce, tie -> smaller index
    #pragma unroll
    for (int rs = 0; rs < 4; rs++) {
        float v  = bv[rs];
        int   ix = bi[rs];
        #pragma unroll
        for (int o = 1; o <= 2; o <<= 1) {
            float v2 = __shfl_xor_sync(~0u, v, o);
            int   i2 = __shfl_xor_sync(~0u, ix, o);
            if (v2 < v || (v2 == v && i2 < ix)) { v = v2; ix = i2; }
        }
        if (t4 == 0) {
            int row = wm * 32 + (rs >> 1) * 16 + (rs & 1) * 8 + g;
            sval[row][wn] = v;
            sidx[row][wn] = ix;
        }
    }
    __syncthreads();

    float lsum = 0.f;
    if (tid < 128) {
        float v  = sval[tid][0];
        int   ix = sidx[tid][0];
        #pragma unroll
        for (int w = 1; w < 4; w++) {
            float v2 = sval[tid][w];
            int   i2 = sidx[tid][w];
            if (v2 < v || (v2 == v && i2 < ix)) { v = v2; ix = i2; }
        }
        int row = m0 + tid;
        out_idx[row] = (float)ix;
        lsum = (v + g_x2[row]) * invN;
    }
    #pragma unroll
    for (int o = 16; o; o >>= 1) lsum += __shfl_xor_sync(~0u, lsum, o);
    if (tid < 128 && lane == 0) atomicAdd(out_loss, lsum);
}

// ---------------------------------------------------------------------------
// Segment scatter-sum: one warp per x row.
// ---------------------------------------------------------------------------
__global__ void segsum_kernel(const float* __restrict__ x,
                              const float* __restrict__ idxf,
                              float* __restrict__ newc,
                              float* __restrict__ cnt, int N) {
    int warp = (blockIdx.x * blockDim.x + threadIdx.x) >> 5;
    int lane = threadIdx.x & 31;
    if (warp >= N) return;
    int k = (int)idxf[warp];
    const float4* row = (const float4*)(x + (size_t)warp * DDIM);
    float* dst = newc + (size_t)k * DDIM;
    #pragma unroll 4
    for (int i = lane; i < DDIM / 4; i += 32) {
        float4 v = row[i];
        atomicAdd(dst + i * 4 + 0, v.x);
        atomicAdd(dst + i * 4 + 1, v.y);
        atomicAdd(dst + i * 4 + 2, v.z);
        atomicAdd(dst + i * 4 + 3, v.w);
    }
    if (lane == 0) atomicAdd(cnt + k, 1.0f);
}

// ---------------------------------------------------------------------------
extern "C" void kernel_launch(void* const* d_in, const int* in_sizes, int n_in,
                              void* d_out, int out_size) {
    const float* x  = (const float*)d_in[0];
    const float* cl = (const float*)d_in[1];
    const int N = in_sizes[0] / DDIM;   // 65536
    float* out = (float*)d_out;

    // Layout: [idx (N) | loss (1) | new_cluster (K*D) | counts (K)]
    float* o_idx  = out;
    float* o_loss = out + N;
    float* o_newc = out + N + 1;
    float* o_cnt  = out + N + 1 + (size_t)KCL * DDIM;

    cudaFuncSetAttribute(assign_mma, cudaFuncAttributeMaxDynamicSharedMemorySize,
                         SMEM_BYTES);

    int nz = 1 + KCL * DDIM + KCL;
    zero_kernel<<<(nz + 255) / 256, 256>>>(o_loss, nz);

    c2_kernel<<<(KCL * 32 + 255) / 256, 256>>>(cl);
    x2_kernel<<<((size_t)N * 32 + 255) / 256, 256>>>(x, N);

    assign_mma<<<N / BM, 512, SMEM_BYTES>>>(x, cl, o_idx, o_loss,
                                            1.0f / (float)N);

    segsum_kernel<<<((size_t)N * 32 + 255) / 256, 256>>>(x, o_idx, o_newc,
                                                         o_cnt, N);
}

// round 5
// speedup vs baseline: 1.0087x; 1.0087x over previous
#include <cuda_runtime.h>
#include <cstdint>

// Problem constants
#define DDIM 512
#define KCL  2048
#define NTOT 65536

// GEMM tiling: CTA 128x128, 256 threads (8 warps, 2Mx4N), warp 64x32, BK=32.
#define BM 128
#define BN 128
#define BK 32
#define NPASS (KCL / BN)        // 16
#define NCH   (DDIM / BK)       // 16
#define TOTC  (NPASS * NCH)     // 256 flattened chunks

// Stage layout (floats): Ahi | Alo | Bhi | Blo, each 128x32
#define AHI_F 0
#define ALO_F 4096
#define BHI_F 8192
#define BLO_F 12288
#define STAGE_F 16384
#define SMEM_BYTES (2 * STAGE_F * 4)   // 128 KB, 2 stages

// Scratch (no cudaMalloc allowed)
__device__ float g_c2[KCL];
__device__ float g_x2[NTOT];

// ---------------------------------------------------------------------------
// Helpers
// ---------------------------------------------------------------------------
// tf32 two-term split: v = h + l (+ eps), both tf32-rounded fp32 values.
__device__ __forceinline__ void split2(float v, float& h, float& l) {
    uint32_t hu; asm("cvt.rna.tf32.f32 %0, %1;" : "=r"(hu) : "f"(v));
    h = __uint_as_float(hu);
    float r = v - h;
    uint32_t lu; asm("cvt.rna.tf32.f32 %0, %1;" : "=r"(lu) : "f"(r));
    l = __uint_as_float(lu);
}

__device__ __forceinline__ void mma8f(float* c, float a0, float a1, float a2,
                                      float a3, float b0, float b1) {
    asm volatile(
        "mma.sync.aligned.m16n8k8.row.col.f32.tf32.tf32.f32 "
        "{%0,%1,%2,%3}, {%4,%5,%6,%7}, {%8,%9}, {%0,%1,%2,%3};"
        : "+f"(c[0]), "+f"(c[1]), "+f"(c[2]), "+f"(c[3])
        : "r"(__float_as_uint(a0)), "r"(__float_as_uint(a1)),
          "r"(__float_as_uint(a2)), "r"(__float_as_uint(a3)),
          "r"(__float_as_uint(b0)), "r"(__float_as_uint(b1)));
}

// Writer: split 8 values (row r, logical cols 8c..8c+7) into hi/lo tiles.
// Tile layout: row-major 32 floats/row; logical col k stored at phys
// (k&3)*8 + (k>>2); 16B groups XOR-swizzled by (r&7). Each compute thread's
// fragment for 2 k-steps is then one conflict-free LDS.128.
// (Layout validated in round 4: rel_err 6.5e-07.)
__device__ __forceinline__ void sts_split8(float* hiB, float* loB, int r, int c,
                                           float4 v0, float4 v1) {
    const int rx = r & 7, ch = c >> 1, e0 = 2 * (c & 1);
    float* hb = hiB + r * 32 + e0;
    float* lb = loB + r * 32 + e0;
    float va[8] = {v0.x, v0.y, v0.z, v0.w, v1.x, v1.y, v1.z, v1.w};
    #pragma unroll
    for (int q = 0; q < 4; q++) {
        float h0, l0, h1, l1;
        split2(va[q],     h0, l0);
        split2(va[q + 4], h1, l1);
        int go = ((2 * q + ch) ^ rx) * 4;
        *(float2*)(hb + go) = make_float2(h0, h1);
        *(float2*)(lb + go) = make_float2(l0, l1);
    }
}

// ---------------------------------------------------------------------------
// Row squared-norms
// ---------------------------------------------------------------------------
__global__ void c2_kernel(const float* __restrict__ cl) {
    int warp = (blockIdx.x * blockDim.x + threadIdx.x) >> 5;
    int lane = threadIdx.x & 31;
    if (warp >= KCL) return;
    const float4* r = (const float4*)(cl + (size_t)warp * DDIM);
    float s = 0.f;
    #pragma unroll 4
    for (int i = lane; i < DDIM / 4; i += 32) {
        float4 v = r[i];
        s += v.x * v.x + v.y * v.y + v.z * v.z + v.w * v.w;
    }
    #pragma unroll
    for (int o = 16; o; o >>= 1) s += __shfl_xor_sync(~0u, s, o);
    if (lane == 0) g_c2[warp] = s;
}

__global__ void x2_kernel(const float* __restrict__ x, int N) {
    int warp = (blockIdx.x * blockDim.x + threadIdx.x) >> 5;
    int lane = threadIdx.x & 31;
    if (warp >= N) return;
    const float4* r = (const float4*)(x + (size_t)warp * DDIM);
    float s = 0.f;
    #pragma unroll 4
    for (int i = lane; i < DDIM / 4; i += 32) {
        float4 v = r[i];
        s += v.x * v.x + v.y * v.y + v.z * v.z + v.w * v.w;
    }
    #pragma unroll
    for (int o = 16; o; o >>= 1) s += __shfl_xor_sync(~0u, s, o);
    if (lane == 0) g_x2[warp] = s;
}

__global__ void zero_kernel(float* p, int n) {
    int i = blockIdx.x * blockDim.x + threadIdx.x;
    if (i < n) p[i] = 0.f;
}

// ---------------------------------------------------------------------------
// mma.sync tf32 (3x split) distance GEMM + fused argmin.
// Pipeline per flattened chunk it = (pass, dc):
//   compute(stage it&1); split+STS regs(it+1) -> stage (it+1)&1; LDG(it+2).
// ---------------------------------------------------------------------------
__global__ void __launch_bounds__(256, 1)
assign_mma(const float* __restrict__ x, const float* __restrict__ cl,
           float* __restrict__ out_idx, float* __restrict__ out_loss,
           float invN) {
    extern __shared__ float smem[];
    __shared__ float sval[128][4];
    __shared__ int   sidx[128][4];

    const int tid  = threadIdx.x;
    const int lane = tid & 31;
    const int wid  = tid >> 5;
    const int wm   = wid & 1;      // 2 warp rows (64 m each)
    const int wn   = wid >> 1;     // 4 warp cols (32 n each)
    const int g    = lane >> 2;
    const int t4   = lane & 3;
    const int m0   = blockIdx.x * BM;

    // writer mapping: row tid>>1, 16 logical cols at 16*(tid&1)
    const int wr = tid >> 1;
    const int wh = tid & 1;

    const float* gA = x + (size_t)m0 * DDIM;

    float acc[4][4][4];
    #pragma unroll
    for (int a = 0; a < 4; a++)
        #pragma unroll
        for (int b = 0; b < 4; b++)
            #pragma unroll
            for (int e = 0; e < 4; e++) acc[a][b][e] = 0.f;

    float bv[8];
    int   bi[8];
    #pragma unroll
    for (int i = 0; i < 8; i++) { bv[i] = 3.4e38f; bi[i] = 0; }

    float4 pa[4], pb[4];   // prefetch regs (16 A floats + 16 B floats)

    #define LDGC(c) do {                                                        \
        int _dc = (c) & (NCH - 1);                                              \
        int _ps = (c) >> 4;                                                     \
        const float* _a = gA + (size_t)wr * DDIM + _dc * BK + wh * 16;          \
        pa[0] = *(const float4*)_a;       pa[1] = *(const float4*)(_a + 4);     \
        pa[2] = *(const float4*)(_a + 8); pa[3] = *(const float4*)(_a + 12);    \
        const float* _b = cl + (size_t)(_ps * BN + wr) * DDIM + _dc * BK + wh * 16; \
        pb[0] = *(const float4*)_b;       pb[1] = *(const float4*)(_b + 4);     \
        pb[2] = *(const float4*)(_b + 8); pb[3] = *(const float4*)(_b + 12);    \
    } while (0)

    #define STSC(stg) do {                                                      \
        sts_split8((stg) + AHI_F, (stg) + ALO_F, wr, 2 * wh,     pa[0], pa[1]); \
        sts_split8((stg) + AHI_F, (stg) + ALO_F, wr, 2 * wh + 1, pa[2], pa[3]); \
        sts_split8((stg) + BHI_F, (stg) + BLO_F, wr, 2 * wh,     pb[0], pb[1]); \
        sts_split8((stg) + BHI_F, (stg) + BLO_F, wr, 2 * wh + 1, pb[2], pb[3]); \
    } while (0)

    // prologue
    LDGC(0);
    STSC(smem);
    LDGC(1);
    __syncthreads();

    #pragma unroll 1
    for (int it = 0; it < TOTC; it++) {
        const float* stage = smem + (it & 1) * STAGE_F;
        const float4* Ah = (const float4*)(stage + AHI_F);
        const float4* Al = (const float4*)(stage + ALO_F);
        const float4* Bh = (const float4*)(stage + BHI_F);
        const float4* Bl = (const float4*)(stage + BLO_F);

        #pragma unroll
        for (int ks2 = 0; ks2 < 2; ks2++) {
            const int sw = (2 * t4 + ks2) ^ g;
            float4 bh[4], bl[4];
            #pragma unroll
            for (int nt = 0; nt < 4; nt++) {
                int rb = wn * 32 + nt * 8 + g;
                bh[nt] = Bh[rb * 8 + sw];
                bl[nt] = Bl[rb * 8 + sw];
            }
            #pragma unroll
            for (int mt = 0; mt < 4; mt++) {
                int ra = wm * 64 + mt * 16 + g;
                float4 ah0 = Ah[ra * 8 + sw], ah1 = Ah[(ra + 8) * 8 + sw];
                float4 al0 = Al[ra * 8 + sw], al1 = Al[(ra + 8) * 8 + sw];
                #pragma unroll
                for (int nt = 0; nt < 4; nt++) {
                    // ks = 2*ks2 (elements .x/.y)
                    mma8f(acc[mt][nt], ah0.x, ah1.x, ah0.y, ah1.y, bh[nt].x, bh[nt].y);
                    mma8f(acc[mt][nt], ah0.x, ah1.x, ah0.y, ah1.y, bl[nt].x, bl[nt].y);
                    mma8f(acc[mt][nt], al0.x, al1.x, al0.y, al1.y, bh[nt].x, bh[nt].y);
                    // ks = 2*ks2+1 (elements .z/.w)
                    mma8f(acc[mt][nt], ah0.z, ah1.z, ah0.w, ah1.w, bh[nt].z, bh[nt].w);
                    mma8f(acc[mt][nt], ah0.z, ah1.z, ah0.w, ah1.w, bl[nt].z, bl[nt].w);
                    mma8f(acc[mt][nt], al0.z, al1.z, al0.w, al1.w, bh[nt].z, bh[nt].w);
                }
            }
        }

        if (it + 1 < TOTC) {
            float* ns = smem + ((it + 1) & 1) * STAGE_F;
            STSC(ns);
        }
        if (it + 2 < TOTC) LDGC(it + 2);

        if ((it & (NCH - 1)) == NCH - 1) {
            // end of pass: fold acc into running argmin, reset acc
            const int kc0 = (it >> 4) * BN;
            #pragma unroll
            for (int mt = 0; mt < 4; mt++)
                #pragma unroll
                for (int hm = 0; hm < 2; hm++) {
                    const int rs = mt * 2 + hm;
                    #pragma unroll
                    for (int nt = 0; nt < 4; nt++)
                        #pragma unroll
                        for (int e = 0; e < 2; e++) {
                            int col = kc0 + wn * 32 + nt * 8 + 2 * t4 + e;
                            float s = fmaf(-2.f, acc[mt][nt][hm * 2 + e],
                                           __ldg(&g_c2[col]));
                            if (s < bv[rs]) { bv[rs] = s; bi[rs] = col; }
                        }
                }
            #pragma unroll
            for (int a = 0; a < 4; a++)
                #pragma unroll
                for (int b = 0; b < 4; b++)
                    #pragma unroll
                    for (int e = 0; e < 4; e++) acc[a][b][e] = 0.f;
        }
        __syncthreads();
    }

    // quad (t4) reduce, tie -> smaller index
    #pragma unroll
    for (int rs = 0; rs < 8; rs++) {
        float v  = bv[rs];
        int   ix = bi[rs];
        #pragma unroll
        for (int o = 1; o <= 2; o <<= 1) {
            float v2 = __shfl_xor_sync(~0u, v, o);
            int   i2 = __shfl_xor_sync(~0u, ix, o);
            if (v2 < v || (v2 == v && i2 < ix)) { v = v2; ix = i2; }
        }
        if (t4 == 0) {
            int row = wm * 64 + (rs >> 1) * 16 + (rs & 1) * 8 + g;
            sval[row][wn] = v;
            sidx[row][wn] = ix;
        }
    }
    __syncthreads();

    float lsum = 0.f;
    if (tid < 128) {
        float v  = sval[tid][0];
        int   ix = sidx[tid][0];
        #pragma unroll
        for (int w = 1; w < 4; w++) {
            float v2 = sval[tid][w];
            int   i2 = sidx[tid][w];
            if (v2 < v || (v2 == v && i2 < ix)) { v = v2; ix = i2; }
        }
        int row = m0 + tid;
        out_idx[row] = (float)ix;
        lsum = (v + g_x2[row]) * invN;
    }
    #pragma unroll
    for (int o = 16; o; o >>= 1) lsum += __shfl_xor_sync(~0u, lsum, o);
    if (tid < 128 && lane == 0) atomicAdd(out_loss, lsum);
}

// ---------------------------------------------------------------------------
// Segment scatter-sum: one warp per x row.
// ---------------------------------------------------------------------------
__global__ void segsum_kernel(const float* __restrict__ x,
                              const float* __restrict__ idxf,
                              float* __restrict__ newc,
                              float* __restrict__ cnt, int N) {
    int warp = (blockIdx.x * blockDim.x + threadIdx.x) >> 5;
    int lane = threadIdx.x & 31;
    if (warp >= N) return;
    int k = (int)idxf[warp];
    const float4* row = (const float4*)(x + (size_t)warp * DDIM);
    float* dst = newc + (size_t)k * DDIM;
    #pragma unroll 4
    for (int i = lane; i < DDIM / 4; i += 32) {
        float4 v = row[i];
        atomicAdd(dst + i * 4 + 0, v.x);
        atomicAdd(dst + i * 4 + 1, v.y);
        atomicAdd(dst + i * 4 + 2, v.z);
        atomicAdd(dst + i * 4 + 3, v.w);
    }
    if (lane == 0) atomicAdd(cnt + k, 1.0f);
}

// ---------------------------------------------------------------------------
extern "C" void kernel_launch(void* const* d_in, const int* in_sizes, int n_in,
                              void* d_out, int out_size) {
    const float* x  = (const float*)d_in[0];
    const float* cl = (const float*)d_in[1];
    const int N = in_sizes[0] / DDIM;   // 65536
    float* out = (float*)d_out;

    // Layout: [idx (N) | loss (1) | new_cluster (K*D) | counts (K)]
    float* o_idx  = out;
    float* o_loss = out + N;
    float* o_newc = out + N + 1;
    float* o_cnt  = out + N + 1 + (size_t)KCL * DDIM;

    cudaFuncSetAttribute(assign_mma, cudaFuncAttributeMaxDynamicSharedMemorySize,
                         SMEM_BYTES);

    int nz = 1 + KCL * DDIM + KCL;
    zero_kernel<<<(nz + 255) / 256, 256>>>(o_loss, nz);

    c2_kernel<<<(KCL * 32 + 255) / 256, 256>>>(cl);
    x2_kernel<<<((size_t)N * 32 + 255) / 256, 256>>>(x, N);

    assign_mma<<<N / BM, 256, SMEM_BYTES>>>(x, cl, o_idx, o_loss,
                                            1.0f / (float)N);

    segsum_kernel<<<((size_t)N * 32 + 255) / 256, 256>>>(x, o_idx, o_newc,
                                                         o_cnt, N);
}

// round 6
// speedup vs baseline: 2.8614x; 2.8367x over previous
#include <cuda_runtime.h>
#include <cstdint>

// Problem constants
#define DDIM 512
#define KCL  2048
#define NTOT 65536

// Phase-1 tiling: CTA 128x256, 256 threads (8 warps 2Mx4N), warp 64x64, BK=32.
#define BM 128
#define BN 256
#define BK 32
#define NPASS (KCL / BN)          // 8
#define NCH   (DDIM / BK)         // 16 chunks per pass
#define TOTC  (NPASS * NCH)       // 128

#define A_ROWS 128
#define B_ROWS 256
#define STAGE_F ((A_ROWS + B_ROWS) * BK)       // 12288 floats = 48 KB
#define B_OFF_F (A_ROWS * BK)                  // 4096
#define NSTAGE 4
#define SMEM_BYTES (NSTAGE * STAGE_F * 4)      // 192 KB

// Scratch
__device__ float    g_c2[KCL];
__device__ uint32_t g_cand[NTOT * 4];

// ---------------------------------------------------------------------------
__device__ __forceinline__ uint32_t smem_to_u32(const void* p) {
    uint32_t a;
    asm("{ .reg .u64 t; cvta.to.shared.u64 t, %1; cvt.u32.u64 %0, t; }"
        : "=r"(a) : "l"(p));
    return a;
}
__device__ __forceinline__ void cp16(uint32_t dst, const void* src) {
    asm volatile("cp.async.cg.shared.global [%0], [%1], 16;"
                 :: "r"(dst), "l"(src) : "memory");
}
#define CP_COMMIT() asm volatile("cp.async.commit_group;" ::: "memory")
#define CP_WAIT(n)  asm volatile("cp.async.wait_group %0;" :: "n"(n) : "memory")

// m16n8k8 tf32 MMA; inputs are raw fp32 regs (HW truncates to tf32).
__device__ __forceinline__ void mma8f(float* c, float a0, float a1, float a2,
                                      float a3, float b0, float b1) {
    asm volatile(
        "mma.sync.aligned.m16n8k8.row.col.f32.tf32.tf32.f32 "
        "{%0,%1,%2,%3}, {%4,%5,%6,%7}, {%8,%9}, {%0,%1,%2,%3};"
        : "+f"(c[0]), "+f"(c[1]), "+f"(c[2]), "+f"(c[3])
        : "r"(__float_as_uint(a0)), "r"(__float_as_uint(a1)),
          "r"(__float_as_uint(a2)), "r"(__float_as_uint(a3)),
          "r"(__float_as_uint(b0)), "r"(__float_as_uint(b1)));
}

__device__ __forceinline__ bool lessVI(float v, int i, float w, int j) {
    return v < w || (v == w && i < j);
}

// ---------------------------------------------------------------------------
// c2 (exact fp32) and output zeroing
// ---------------------------------------------------------------------------
__global__ void c2_kernel(const float* __restrict__ cl) {
    int warp = (blockIdx.x * blockDim.x + threadIdx.x) >> 5;
    int lane = threadIdx.x & 31;
    if (warp >= KCL) return;
    const float4* r = (const float4*)(cl + (size_t)warp * DDIM);
    float s = 0.f;
    #pragma unroll 4
    for (int i = lane; i < DDIM / 4; i += 32) {
        float4 v = r[i];
        s += v.x * v.x + v.y * v.y + v.z * v.z + v.w * v.w;
    }
    #pragma unroll
    for (int o = 16; o; o >>= 1) s += __shfl_xor_sync(~0u, s, o);
    if (lane == 0) g_c2[warp] = s;
}

__global__ void zero_kernel(float* p, int n) {
    int i = blockIdx.x * blockDim.x + threadIdx.x;
    if (i < n) p[i] = 0.f;
}

// ---------------------------------------------------------------------------
// Phase 1: approximate distance GEMM (single tf32 MMA) + per-lane top-2,
// merged to per-row top-4 candidates.
// smem row: 32 floats = 8 float4-groups, group q of row r at q ^ (r & 7).
// ---------------------------------------------------------------------------
__global__ void __launch_bounds__(256, 1)
assign_approx(const float* __restrict__ x, const float* __restrict__ cl) {
    extern __shared__ float smem[];
    const uint32_t sb = smem_to_u32(smem);

    const int tid  = threadIdx.x;
    const int lane = tid & 31;
    const int wid  = tid >> 5;
    const int wm   = wid & 1;       // 2 warp rows (64 m)
    const int wn   = wid >> 1;      // 4 warp cols (64 n)
    const int g    = lane >> 2;
    const int t4   = lane & 3;
    const int m0   = blockIdx.x * BM;

    // cp.async loader for flattened chunk c (pass = c>>4, dc = c&15)
    #define LDGC(c, stg) do {                                                   \
        int _dc = (c) & (NCH - 1);                                              \
        int _ps = (c) >> 4;                                                     \
        int _d0 = _dc * BK;                                                     \
        uint32_t _sa = sb + (uint32_t)(stg) * (STAGE_F * 4);                    \
        _Pragma("unroll")                                                       \
        for (int i = 0; i < 4; i++) {                                           \
            int v = tid + 256 * i, r = v >> 3, q = v & 7;                       \
            cp16(_sa + r * 128 + ((q ^ (r & 7)) * 16),                          \
                 x + (size_t)(m0 + r) * DDIM + _d0 + q * 4);                    \
        }                                                                       \
        uint32_t _sbB = _sa + B_OFF_F * 4;                                      \
        _Pragma("unroll")                                                       \
        for (int i = 0; i < 8; i++) {                                           \
            int v = tid + 256 * i, r = v >> 3, q = v & 7;                       \
            cp16(_sbB + r * 128 + ((q ^ (r & 7)) * 16),                         \
                 cl + (size_t)(_ps * BN + r) * DDIM + _d0 + q * 4);             \
        }                                                                       \
    } while (0)

    float acc[4][8][4];
    #pragma unroll
    for (int a = 0; a < 4; a++)
        #pragma unroll
        for (int b = 0; b < 8; b++)
            #pragma unroll
            for (int e = 0; e < 4; e++) acc[a][b][e] = 0.f;

    // per-slot (8 rows/thread) top-2 over this thread's column subset
    float bv1[8], bv2[8];
    int   bi1[8], bi2[8];
    #pragma unroll
    for (int i = 0; i < 8; i++) {
        bv1[i] = 3.4e38f; bv2[i] = 3.4e38f; bi1[i] = 0; bi2[i] = 0;
    }

    // prologue: 3 stages in flight
    LDGC(0, 0); CP_COMMIT();
    LDGC(1, 1); CP_COMMIT();
    LDGC(2, 2); CP_COMMIT();

    #pragma unroll 1
    for (int it = 0; it < TOTC; it++) {
        CP_WAIT(2);
        __syncthreads();

        if (it + 3 < TOTC) { LDGC(it + 3, (it + 3) & 3); }
        CP_COMMIT();

        const float* SA = smem + (it & 3) * STAGE_F;
        const float* SB = SA + B_OFF_F;

        #pragma unroll
        for (int ks = 0; ks < 4; ks++) {
            const int sw0 = ((2 * ks)     ^ g) * 4 + t4;
            const int sw1 = ((2 * ks + 1) ^ g) * 4 + t4;
            float b0[8], b1[8];
            #pragma unroll
            for (int nt = 0; nt < 8; nt++) {
                int rb = (wn * 64 + nt * 8 + g) * 32;
                b0[nt] = SB[rb + sw0];
                b1[nt] = SB[rb + sw1];
            }
            #pragma unroll
            for (int mt = 0; mt < 4; mt++) {
                int ra = (wm * 64 + mt * 16 + g) * 32;
                float a0 = SA[ra + sw0];
                float a1 = SA[ra + 256 + sw0];   // row +8
                float a2 = SA[ra + sw1];
                float a3 = SA[ra + 256 + sw1];
                #pragma unroll
                for (int nt = 0; nt < 8; nt++)
                    mma8f(acc[mt][nt], a0, a1, a2, a3, b0[nt], b1[nt]);
            }
        }

        if ((it & (NCH - 1)) == NCH - 1) {
            // pass epilogue: d2a = c2 - 2*dot, fold into per-slot top-2
            const int kcb = (it >> 4) * BN + wn * 64;
            float c2v[16];
            #pragma unroll
            for (int nt = 0; nt < 8; nt++) {
                c2v[nt * 2]     = __ldg(&g_c2[kcb + nt * 8 + 2 * t4]);
                c2v[nt * 2 + 1] = __ldg(&g_c2[kcb + nt * 8 + 2 * t4 + 1]);
            }
            #pragma unroll
            for (int mt = 0; mt < 4; mt++)
                #pragma unroll
                for (int e = 0; e < 4; e++) {
                    const int rs = mt * 2 + (e >> 1);
                    #pragma unroll
                    for (int nt = 0; nt < 8; nt++) {
                        float v = fmaf(-2.f, acc[mt][nt][e],
                                       c2v[nt * 2 + (e & 1)]);
                        int col = kcb + nt * 8 + 2 * t4 + (e & 1);
                        if (v < bv1[rs]) {
                            bv2[rs] = bv1[rs]; bi2[rs] = bi1[rs];
                            bv1[rs] = v;       bi1[rs] = col;
                        } else if (v < bv2[rs]) {
                            bv2[rs] = v;       bi2[rs] = col;
                        }
                    }
                }
            #pragma unroll
            for (int a = 0; a < 4; a++)
                #pragma unroll
                for (int b = 0; b < 8; b++)
                    #pragma unroll
                    for (int e = 0; e < 4; e++) acc[a][b][e] = 0.f;
        }
    }

    // Merge: dump per-lane top-2 to smem; one thread per row picks top-4.
    __syncthreads();
    float* sv = smem;                      // [128][32]
    int*   si = (int*)(smem + 4096);       // [128][32]
    #pragma unroll
    for (int rs = 0; rs < 8; rs++) {
        int row = wm * 64 + (rs >> 1) * 16 + (rs & 1) * 8 + g;
        int e = row * 32 + wn * 8 + t4 * 2;
        sv[e]     = bv1[rs];  si[e]     = bi1[rs];
        sv[e + 1] = bv2[rs];  si[e + 1] = bi2[rs];
    }
    __syncthreads();

    if (tid < 128) {
        float v4[4] = {3.4e38f, 3.4e38f, 3.4e38f, 3.4e38f};
        int   i4[4] = {0x7fffffff, 0x7fffffff, 0x7fffffff, 0x7fffffff};
        #pragma unroll 4
        for (int e = 0; e < 32; e++) {
            float v = sv[tid * 32 + e];
            int   ix = si[tid * 32 + e];
            if (lessVI(v, ix, v4[3], i4[3])) {
                v4[3] = v; i4[3] = ix;
                #pragma unroll
                for (int k = 3; k > 0; k--)
                    if (lessVI(v4[k], i4[k], v4[k - 1], i4[k - 1])) {
                        float tv = v4[k]; v4[k] = v4[k - 1]; v4[k - 1] = tv;
                        int   ti = i4[k]; i4[k] = i4[k - 1]; i4[k - 1] = ti;
                    }
            }
        }
        #pragma unroll
        for (int j = 0; j < 4; j++)
            g_cand[(size_t)(m0 + tid) * 4 + j] = (uint32_t)i4[j];
    }
}

// ---------------------------------------------------------------------------
// Phase 2: exact fp32 rescore of 4 candidates + idx/loss + fused scatter.
// One warp per row; 256 threads = 8 rows per block.
// ---------------------------------------------------------------------------
__global__ void __launch_bounds__(256)
finalize_kernel(const float* __restrict__ x, const float* __restrict__ cl,
                float* __restrict__ out_idx, float* __restrict__ out_loss,
                float* __restrict__ newc, float* __restrict__ cnt,
                float invN) {
    __shared__ float ls[8];
    const int tid  = threadIdx.x;
    const int lane = tid & 31;
    const int wid  = tid >> 5;
    const int row  = blockIdx.x * 8 + wid;

    const float4* X4 = (const float4*)(x + (size_t)row * DDIM);
    float4 xf[4];
    #pragma unroll
    for (int t = 0; t < 4; t++) xf[t] = X4[lane + 32 * t];

    float px = 0.f;
    #pragma unroll
    for (int t = 0; t < 4; t++)
        px += xf[t].x * xf[t].x + xf[t].y * xf[t].y +
              xf[t].z * xf[t].z + xf[t].w * xf[t].w;
    #pragma unroll
    for (int o = 16; o; o >>= 1) px += __shfl_xor_sync(~0u, px, o);
    const float x2 = px;

    float bestv = 3.4e38f;
    int   besti = 0x7fffffff;
    #pragma unroll
    for (int j = 0; j < 4; j++) {
        int k = (int)g_cand[(size_t)row * 4 + j];
        const float4* C4 = (const float4*)(cl + (size_t)k * DDIM);
        float pd = 0.f;
        #pragma unroll
        for (int t = 0; t < 4; t++) {
            float4 cv = C4[lane + 32 * t];
            pd = fmaf(xf[t].x, cv.x, pd);
            pd = fmaf(xf[t].y, cv.y, pd);
            pd = fmaf(xf[t].z, cv.z, pd);
            pd = fmaf(xf[t].w, cv.w, pd);
        }
        #pragma unroll
        for (int o = 16; o; o >>= 1) pd += __shfl_xor_sync(~0u, pd, o);
        float d2 = x2 + g_c2[k] - 2.f * pd;
        if (lessVI(d2, k, bestv, besti)) { bestv = d2; besti = k; }
    }

    if (lane == 0) {
        out_idx[row] = (float)besti;
        atomicAdd(cnt + besti, 1.0f);
        ls[wid] = bestv;
    }
    __syncthreads();
    if (tid == 0) {
        float s = 0.f;
        #pragma unroll
        for (int w = 0; w < 8; w++) s += ls[w];
        atomicAdd(out_loss, s * invN);
    }

    // scatter x row into new_cluster[besti]
    float* dst = newc + (size_t)besti * DDIM;
    #pragma unroll
    for (int t = 0; t < 4; t++) {
        int b = (lane + 32 * t) * 4;
        atomicAdd(dst + b + 0, xf[t].x);
        atomicAdd(dst + b + 1, xf[t].y);
        atomicAdd(dst + b + 2, xf[t].z);
        atomicAdd(dst + b + 3, xf[t].w);
    }
}

// ---------------------------------------------------------------------------
extern "C" void kernel_launch(void* const* d_in, const int* in_sizes, int n_in,
                              void* d_out, int out_size) {
    const float* x  = (const float*)d_in[0];
    const float* cl = (const float*)d_in[1];
    const int N = in_sizes[0] / DDIM;   // 65536
    float* out = (float*)d_out;

    // Layout: [idx (N) | loss (1) | new_cluster (K*D) | counts (K)]
    float* o_idx  = out;
    float* o_loss = out + N;
    float* o_newc = out + N + 1;
    float* o_cnt  = out + N + 1 + (size_t)KCL * DDIM;

    cudaFuncSetAttribute(assign_approx,
                         cudaFuncAttributeMaxDynamicSharedMemorySize, SMEM_BYTES);

    int nz = 1 + KCL * DDIM + KCL;
    zero_kernel<<<(nz + 255) / 256, 256>>>(o_loss, nz);

    c2_kernel<<<(KCL * 32 + 255) / 256, 256>>>(cl);

    assign_approx<<<N / BM, 256, SMEM_BYTES>>>(x, cl);

    finalize_kernel<<<N / 8, 256>>>(x, cl, o_idx, o_loss, o_newc, o_cnt,
                                    1.0f / (float)N);
}